// round 1
// baseline (speedup 1.0000x reference)
#include <cuda_runtime.h>
#include <math.h>

#define Bn 4096
#define Ln 30
#define Wn 5
#define An 30
#define En 128
#define Cn 40
#define Hn 128
#define Tn 3
#define LINn 200
#define Nn (Bn*Ln)          // 122880 tokens
#define G4n (4*Hn)          // 512
#define GALLn (8*Hn)        // 1024 (fwd 0..511, bwd 512..1023)
#define EPS 1e-5f

// ---------------- static device scratch (no allocations allowed) ----------------
__device__ float g_scale1[Cn];
__device__ float g_shift1[Cn];
__device__ float g_P[An*Cn*3];          // folded conv*bn scale lookup table
__device__ float g_s2[2*Hn];
__device__ float g_sh2[2*Hn];
__device__ float g_fcw2[Tn*2*Hn];       // fc_w * bn2 scale
__device__ float g_fcb2[Tn];            // fc_b + fc_w @ bn2 shift
__device__ float g_Bmat[LINn*GALLn];    // [k][g] concatenated w_ih_f / w_ih_b (transposed)
__device__ float g_biascat[GALLn];
__device__ float g_feat[(size_t)Nn*LINn];       // 98 MB
__device__ float g_xproj[(size_t)Nn*GALLn];     // 503 MB
__device__ float g_hf[(size_t)Nn*Hn];           // 63 MB
__device__ float g_hb[(size_t)Nn*Hn];           // 63 MB
__device__ float g_emis[Nn*Tn];

// ---------------- prep kernels ----------------
__global__ void prep_small(const float* conv_b, const float* bn1_g, const float* bn1_b,
                           const float* bn1_m, const float* bn1_v,
                           const float* bn2_g, const float* bn2_b, const float* bn2_m,
                           const float* bn2_v, const float* fc_w, const float* fc_b,
                           const float* b_f, const float* b_b) {
    int tid = threadIdx.x;
    if (tid < Cn) {
        float s = bn1_g[tid] / sqrtf(bn1_v[tid] + EPS);
        g_scale1[tid] = s;
        g_shift1[tid] = (conv_b[tid] - bn1_m[tid]) * s + bn1_b[tid];
    }
    if (tid < 2*Hn) {
        float s = bn2_g[tid] / sqrtf(bn2_v[tid] + EPS);
        g_s2[tid] = s;
        g_sh2[tid] = bn2_b[tid] - bn2_m[tid] * s;
    }
    __syncthreads();
    for (int i = tid; i < Tn*2*Hn; i += 256)
        g_fcw2[i] = fc_w[i] * g_s2[i % (2*Hn)];
    if (tid < Tn) {
        float acc = fc_b[tid];
        for (int j = 0; j < 2*Hn; j++) acc += fc_w[tid*2*Hn + j] * g_sh2[j];
        g_fcb2[tid] = acc;
    }
    for (int i = tid; i < GALLn; i += 256)
        g_biascat[i] = (i < G4n) ? b_f[i] : b_b[i - G4n];
}

__global__ void prep_P(const float* emb, const float* conv_w) {
    int idx = blockIdx.x*blockDim.x + threadIdx.x;
    if (idx >= An*Cn*3) return;
    int k = idx % 3;
    int c = (idx/3) % Cn;
    int a = idx/(3*Cn);
    float acc = 0.f;
    for (int e = 0; e < En; e++)
        acc += emb[a*En + e] * conv_w[(c*En + e)*3 + k];
    g_P[(a*Cn + c)*3 + k] = acc * g_scale1[c];
}

__global__ void prep_Bmat(const float* w_ih_f, const float* w_ih_b) {
    int idx = blockIdx.x*blockDim.x + threadIdx.x;
    if (idx >= LINn*GALLn) return;
    int g = idx % GALLn;
    int k = idx / GALLn;
    g_Bmat[idx] = (g < G4n) ? w_ih_f[g*LINn + k] : w_ih_b[(g - G4n)*LINn + k];
}

// ---------------- feature kernel: conv(table)+bn+relu+maxpool ----------------
__global__ void feat_kernel(const int* __restrict__ x) {
    __shared__ float sP[An*Cn*3];
    __shared__ float sSh[Cn];
    for (int i = threadIdx.x; i < An*Cn*3; i += blockDim.x) sP[i] = g_P[i];
    if (threadIdx.x < Cn) sSh[threadIdx.x] = g_shift1[threadIdx.x];
    __syncthreads();
    int gi = blockIdx.x*blockDim.x + threadIdx.x;
    if (gi >= Nn*Cn) return;
    int c = gi % Cn;
    int n = gi / Cn;
    int xi[Wn];
    #pragma unroll
    for (int j = 0; j < Wn; j++) xi[j] = x[n*Wn + j];
    float r[Wn];
    #pragma unroll
    for (int w = 0; w < Wn; w++) {
        float v = sSh[c];
        if (w-1 >= 0) v += sP[(xi[w-1]*Cn + c)*3 + 0];
        v += sP[(xi[w]*Cn + c)*3 + 1];
        if (w+1 < Wn) v += sP[(xi[w+1]*Cn + c)*3 + 2];
        r[w] = fmaxf(v, 0.f);
    }
    float* fo = &g_feat[(size_t)n*LINn + c*Wn];
    #pragma unroll
    for (int w = 0; w < Wn; w++) {
        float m = r[w];
        if (w-1 >= 0) m = fmaxf(m, r[w-1]);
        if (w+1 < Wn) m = fmaxf(m, r[w+1]);
        fo[w] = m;
    }
}

// ---------------- input-projection GEMM: [N,200]@[200,1024]+bias ----------------
#define BM 64
#define BN 64
#define BK 16
__global__ void gemm_kernel() {
    __shared__ float As[BK][BM+4];
    __shared__ float Bs[BK][BN];
    int tx = threadIdx.x % 16;
    int ty = threadIdx.x / 16;
    int row0 = blockIdx.y * BM;
    int col0 = blockIdx.x * BN;
    float acc[4][4];
    #pragma unroll
    for (int i = 0; i < 4; i++)
        #pragma unroll
        for (int j = 0; j < 4; j++) acc[i][j] = 0.f;

    for (int k0 = 0; k0 < LINn; k0 += BK) {
        for (int i = threadIdx.x; i < BM*BK; i += 256) {
            int m = i / BK, k = i % BK;
            As[k][m] = (k0 + k < LINn) ? g_feat[(size_t)(row0 + m)*LINn + k0 + k] : 0.f;
        }
        for (int i = threadIdx.x; i < BK*BN; i += 256) {
            int k = i / BN, c = i % BN;
            Bs[k][c] = (k0 + k < LINn) ? g_Bmat[(k0 + k)*GALLn + col0 + c] : 0.f;
        }
        __syncthreads();
        #pragma unroll
        for (int kk = 0; kk < BK; kk++) {
            float a[4], b[4];
            #pragma unroll
            for (int i = 0; i < 4; i++) a[i] = As[kk][ty*4 + i];
            #pragma unroll
            for (int j = 0; j < 4; j++) b[j] = Bs[kk][tx*4 + j];
            #pragma unroll
            for (int i = 0; i < 4; i++)
                #pragma unroll
                for (int j = 0; j < 4; j++) acc[i][j] += a[i]*b[j];
        }
        __syncthreads();
    }
    #pragma unroll
    for (int i = 0; i < 4; i++)
        #pragma unroll
        for (int j = 0; j < 4; j++)
            g_xproj[(size_t)(row0 + ty*4 + i)*GALLn + col0 + tx*4 + j] =
                acc[i][j] + g_biascat[col0 + tx*4 + j];
}

// ---------------- LSTM recurrence (both directions, block-resident batch) -------
// block = 256 thr, 32 samples; thread owns 4 samples x 4 hidden-units x 4 gates.
#define LSTM_SMEM ((32*129 + 32*513)*4)
__device__ __forceinline__ float sigf(float v) { return 1.f / (1.f + expf(-v)); }

__global__ void lstm_kernel(const float* __restrict__ w_hh_f,
                            const float* __restrict__ w_hh_b) {
    extern __shared__ float sm[];
    float* hs = sm;                 // [32][129]
    float* wt = sm + 32*129;        // [32][513]
    int dir = blockIdx.y;
    const float* Whh = dir ? w_hh_b : w_hh_f;
    float* hout = dir ? g_hb : g_hf;
    int b0 = blockIdx.x * 32;
    int tid = threadIdx.x;
    int sg = tid & 7;               // sample group (4 samples each)
    int ug = tid >> 3;              // unit group (4 units each)

    // init state
    for (int i = tid; i < 32*129; i += 256) hs[i] = 0.f;
    float cReg[4][4];
    #pragma unroll
    for (int si = 0; si < 4; si++)
        #pragma unroll
        for (int q = 0; q < 4; q++) cReg[si][q] = 0.f;
    __syncthreads();

    for (int t = 0; t < Ln; t++) {
        int tt = dir ? (Ln - 1 - t) : t;
        float acc[4][16];
        #pragma unroll
        for (int si = 0; si < 4; si++)
            #pragma unroll
            for (int j = 0; j < 16; j++) acc[si][j] = 0.f;

        for (int k0 = 0; k0 < Hn; k0 += 32) {
            __syncthreads();
            for (int idx = tid; idx < G4n*32; idx += 256) {
                int g = idx >> 5, kl = idx & 31;
                wt[kl*513 + g] = Whh[g*Hn + k0 + kl];      // coalesced gmem read
            }
            __syncthreads();
            #pragma unroll 4
            for (int kl = 0; kl < 32; kl++) {
                float hv[4];
                #pragma unroll
                for (int si = 0; si < 4; si++) hv[si] = hs[(sg*4 + si)*129 + k0 + kl];
                const float* wrow = &wt[kl*513];
                #pragma unroll
                for (int q = 0; q < 4; q++) {
                    int u = ug*4 + q;
                    float w0 = wrow[u];
                    float w1 = wrow[u + 128];
                    float w2 = wrow[u + 256];
                    float w3 = wrow[u + 384];
                    #pragma unroll
                    for (int si = 0; si < 4; si++) {
                        acc[si][q*4+0] += hv[si]*w0;
                        acc[si][q*4+1] += hv[si]*w1;
                        acc[si][q*4+2] += hv[si]*w2;
                        acc[si][q*4+3] += hv[si]*w3;
                    }
                }
            }
        }
        __syncthreads();   // all hs reads done before updating hs

        #pragma unroll
        for (int si = 0; si < 4; si++) {
            int s = sg*4 + si;
            int n = (b0 + s)*Ln + tt;
            const float* xp = &g_xproj[(size_t)n*GALLn + dir*G4n];
            #pragma unroll
            for (int q = 0; q < 4; q++) {
                int u = ug*4 + q;
                float zi = acc[si][q*4+0] + xp[u];
                float zf = acc[si][q*4+1] + xp[u + 128];
                float zg = acc[si][q*4+2] + xp[u + 256];
                float zo = acc[si][q*4+3] + xp[u + 384];
                float cn = sigf(zf)*cReg[si][q] + sigf(zi)*tanhf(zg);
                float hn = sigf(zo)*tanhf(cn);
                cReg[si][q] = cn;
                hs[s*129 + u] = hn;
                hout[(size_t)n*Hn + u] = hn;
            }
        }
        __syncthreads();
    }
}

// ---------------- emissions: bn2+fc folded, warp per token ----------------
__global__ void emis_kernel() {
    int gtid = blockIdx.x*blockDim.x + threadIdx.x;
    int w = gtid >> 5;
    int lane = gtid & 31;
    if (w >= Nn) return;
    float a0 = 0.f, a1 = 0.f, a2 = 0.f;
    for (int j = lane; j < 2*Hn; j += 32) {
        float hv = (j < Hn) ? g_hf[(size_t)w*Hn + j] : g_hb[(size_t)w*Hn + j - Hn];
        a0 += hv * g_fcw2[0*2*Hn + j];
        a1 += hv * g_fcw2[1*2*Hn + j];
        a2 += hv * g_fcw2[2*2*Hn + j];
    }
    #pragma unroll
    for (int off = 16; off; off >>= 1) {
        a0 += __shfl_xor_sync(0xffffffffu, a0, off);
        a1 += __shfl_xor_sync(0xffffffffu, a1, off);
        a2 += __shfl_xor_sync(0xffffffffu, a2, off);
    }
    if (lane == 0) {
        g_emis[w*Tn + 0] = a0 + g_fcb2[0];
        g_emis[w*Tn + 1] = a1 + g_fcb2[1];
        g_emis[w*Tn + 2] = a2 + g_fcb2[2];
    }
}

// ---------------- viterbi: one thread per sample ----------------
__global__ void viterbi_kernel(const int* __restrict__ x,
                               const float* __restrict__ trans,
                               const float* __restrict__ start_t,
                               const float* __restrict__ end_t,
                               float* __restrict__ out) {
    int b = blockIdx.x*blockDim.x + threadIdx.x;
    if (b >= Bn) return;
    float tr[Tn][Tn];
    #pragma unroll
    for (int i = 0; i < Tn; i++)
        #pragma unroll
        for (int j = 0; j < Tn; j++) tr[i][j] = trans[i*Tn + j];

    float sc[Tn];
    #pragma unroll
    for (int j = 0; j < Tn; j++) sc[j] = start_t[j] + g_emis[(b*Ln)*Tn + j];

    unsigned char hist[Ln-1][Tn];
    for (int t = 1; t < Ln; t++) {
        bool m = x[(b*Ln + t)*Wn + 2] > 0;
        float ns[Tn];
        #pragma unroll
        for (int j = 0; j < Tn; j++) {
            float best = sc[0] + tr[0][j];
            int bi = 0;
            #pragma unroll
            for (int i = 1; i < Tn; i++) {
                float v = sc[i] + tr[i][j];
                if (v > best) { best = v; bi = i; }   // first-max (jnp.argmax)
            }
            hist[t-1][j] = (unsigned char)bi;
            ns[j] = best + g_emis[(b*Ln + t)*Tn + j];
        }
        if (m) {
            #pragma unroll
            for (int j = 0; j < Tn; j++) sc[j] = ns[j];
        }
    }
    #pragma unroll
    for (int j = 0; j < Tn; j++) sc[j] += end_t[j];
    float best = sc[0];
    int last = 0;
    #pragma unroll
    for (int j = 1; j < Tn; j++) if (sc[j] > best) { best = sc[j]; last = j; }

    int tags[Ln];
    tags[Ln-1] = last;
    int tag = last;
    for (int t = Ln-1; t >= 1; t--) {
        bool m = x[(b*Ln + t)*Wn + 2] > 0;
        int prev = hist[t-1][tag];
        if (m) tag = prev;
        tags[t-1] = tag;
    }
    out[b] = best;
    float* to = out + Bn + (size_t)b*Ln;
    for (int l = 0; l < Ln; l++) to[l] = (float)tags[l];
}

// ---------------- launch ----------------
extern "C" void kernel_launch(void* const* d_in, const int* in_sizes, int n_in,
                              void* d_out, int out_size) {
    const int*   x      = (const int*)  d_in[0];
    const float* emb    = (const float*)d_in[1];
    const float* conv_w = (const float*)d_in[2];
    const float* conv_b = (const float*)d_in[3];
    const float* bn1_g  = (const float*)d_in[4];
    const float* bn1_b  = (const float*)d_in[5];
    const float* bn1_m  = (const float*)d_in[6];
    const float* bn1_v  = (const float*)d_in[7];
    const float* w_ih_f = (const float*)d_in[8];
    const float* w_hh_f = (const float*)d_in[9];
    const float* b_f    = (const float*)d_in[10];
    const float* w_ih_b = (const float*)d_in[11];
    const float* w_hh_b = (const float*)d_in[12];
    const float* b_b    = (const float*)d_in[13];
    const float* bn2_g  = (const float*)d_in[14];
    const float* bn2_b  = (const float*)d_in[15];
    const float* bn2_m  = (const float*)d_in[16];
    const float* bn2_v  = (const float*)d_in[17];
    const float* fc_w   = (const float*)d_in[18];
    const float* fc_b   = (const float*)d_in[19];
    const float* trans  = (const float*)d_in[20];
    const float* startt = (const float*)d_in[21];
    const float* endt   = (const float*)d_in[22];
    float* out = (float*)d_out;

    prep_small<<<1, 256>>>(conv_b, bn1_g, bn1_b, bn1_m, bn1_v,
                           bn2_g, bn2_b, bn2_m, bn2_v, fc_w, fc_b, b_f, b_b);
    prep_P<<<(An*Cn*3 + 255)/256, 256>>>(emb, conv_w);
    prep_Bmat<<<(LINn*GALLn + 255)/256, 256>>>(w_ih_f, w_ih_b);
    feat_kernel<<<(Nn*Cn + 255)/256, 256>>>(x);
    gemm_kernel<<<dim3(GALLn/BN, Nn/BM), 256>>>();
    cudaFuncSetAttribute(lstm_kernel, cudaFuncAttributeMaxDynamicSharedMemorySize, LSTM_SMEM);
    lstm_kernel<<<dim3(Bn/32, 2), 256, LSTM_SMEM>>>(w_hh_f, w_hh_b);
    emis_kernel<<<(Nn*32 + 255)/256, 256>>>();
    viterbi_kernel<<<(Bn + 255)/256, 256>>>(x, trans, startt, endt, out);
}

// round 5
// speedup vs baseline: 1.5119x; 1.5119x over previous
#include <cuda_runtime.h>
#include <math.h>

#define Bn 4096
#define Ln 30
#define Wn 5
#define An 30
#define En 128
#define Cn 40
#define Hn 128
#define Tn 3
#define LINn 200
#define Nn (Bn*Ln)          // 122880 tokens
#define G4n (4*Hn)          // 512
#define GALLn (8*Hn)        // 1024 (fwd 0..511, bwd 512..1023)
#define EPS 1e-5f

typedef unsigned long long u64t;

// packed fp32x2 FMA (Blackwell): d = a*b + d, two fp32 lanes per instruction
__device__ __forceinline__ void fma2(u64t& d, u64t a, u64t b) {
    asm("fma.rn.f32x2 %0, %1, %2, %0;" : "+l"(d) : "l"(a), "l"(b));
}
__device__ __forceinline__ u64t pk2(float lo, float hi) {
    u64t r; asm("mov.b64 %0, {%1, %2};" : "=l"(r) : "f"(lo), "f"(hi)); return r;
}
__device__ __forceinline__ float2 upk(u64t v) {
    float2 r; asm("mov.b64 {%0, %1}, %2;" : "=f"(r.x), "=f"(r.y) : "l"(v)); return r;
}

// ---------------- static device scratch ----------------
__device__ float g_scale1[Cn];
__device__ float g_shift1[Cn];
__device__ float g_P[An*Cn*3];
__device__ float g_s2[2*Hn];
__device__ float g_sh2[2*Hn];
__device__ float g_fcw2[Tn*2*Hn];
__device__ float g_fcb2[Tn];
__device__ float g_Bmat[LINn*GALLn];
__device__ float g_biascat[GALLn];
__device__ float g_feat[(size_t)Nn*LINn];
__device__ float g_xproj[(size_t)Nn*GALLn];
__device__ float g_hf[(size_t)Nn*Hn];
__device__ float g_hb[(size_t)Nn*Hn];
__device__ float g_emis[Nn*Tn];

// ---------------- prep kernels ----------------
__global__ void prep_small(const float* conv_b, const float* bn1_g, const float* bn1_b,
                           const float* bn1_m, const float* bn1_v,
                           const float* bn2_g, const float* bn2_b, const float* bn2_m,
                           const float* bn2_v, const float* fc_w, const float* fc_b,
                           const float* b_f, const float* b_b) {
    int tid = threadIdx.x;
    if (tid < Cn) {
        float s = bn1_g[tid] / sqrtf(bn1_v[tid] + EPS);
        g_scale1[tid] = s;
        g_shift1[tid] = (conv_b[tid] - bn1_m[tid]) * s + bn1_b[tid];
    }
    if (tid < 2*Hn) {
        float s = bn2_g[tid] / sqrtf(bn2_v[tid] + EPS);
        g_s2[tid] = s;
        g_sh2[tid] = bn2_b[tid] - bn2_m[tid] * s;
    }
    __syncthreads();
    for (int i = tid; i < Tn*2*Hn; i += 256)
        g_fcw2[i] = fc_w[i] * g_s2[i % (2*Hn)];
    if (tid < Tn) {
        float acc = fc_b[tid];
        for (int j = 0; j < 2*Hn; j++) acc += fc_w[tid*2*Hn + j] * g_sh2[j];
        g_fcb2[tid] = acc;
    }
    for (int i = tid; i < GALLn; i += 256)
        g_biascat[i] = (i < G4n) ? b_f[i] : b_b[i - G4n];
}

__global__ void prep_P(const float* emb, const float* conv_w) {
    int idx = blockIdx.x*blockDim.x + threadIdx.x;
    if (idx >= An*Cn*3) return;
    int k = idx % 3;
    int c = (idx/3) % Cn;
    int a = idx/(3*Cn);
    float acc = 0.f;
    for (int e = 0; e < En; e++)
        acc += emb[a*En + e] * conv_w[(c*En + e)*3 + k];
    g_P[(a*Cn + c)*3 + k] = acc * g_scale1[c];
}

__global__ void prep_Bmat(const float* w_ih_f, const float* w_ih_b) {
    int idx = blockIdx.x*blockDim.x + threadIdx.x;
    if (idx >= LINn*GALLn) return;
    int g = idx % GALLn;
    int k = idx / GALLn;
    g_Bmat[idx] = (g < G4n) ? w_ih_f[g*LINn + k] : w_ih_b[(g - G4n)*LINn + k];
}

// ---------------- feature kernel: conv(table)+bn+relu+maxpool ----------------
__global__ void feat_kernel(const int* __restrict__ x) {
    __shared__ float sP[An*Cn*3];
    __shared__ float sSh[Cn];
    for (int i = threadIdx.x; i < An*Cn*3; i += blockDim.x) sP[i] = g_P[i];
    if (threadIdx.x < Cn) sSh[threadIdx.x] = g_shift1[threadIdx.x];
    __syncthreads();
    int gi = blockIdx.x*blockDim.x + threadIdx.x;
    if (gi >= Nn*Cn) return;
    int c = gi % Cn;
    int n = gi / Cn;
    int xi[Wn];
    #pragma unroll
    for (int j = 0; j < Wn; j++) xi[j] = x[n*Wn + j];
    float r[Wn];
    #pragma unroll
    for (int w = 0; w < Wn; w++) {
        float v = sSh[c];
        if (w-1 >= 0) v += sP[(xi[w-1]*Cn + c)*3 + 0];
        v += sP[(xi[w]*Cn + c)*3 + 1];
        if (w+1 < Wn) v += sP[(xi[w+1]*Cn + c)*3 + 2];
        r[w] = fmaxf(v, 0.f);
    }
    float* fo = &g_feat[(size_t)n*LINn + c*Wn];
    #pragma unroll
    for (int w = 0; w < Wn; w++) {
        float m = r[w];
        if (w-1 >= 0) m = fmaxf(m, r[w-1]);
        if (w+1 < Wn) m = fmaxf(m, r[w+1]);
        fo[w] = m;
    }
}

// ---------------- input-projection GEMM: [N,200]@[200,1024]+bias, f32x2 ----------
#define GBM 128
#define GBN 128
#define GBK 8
__global__ void gemm_kernel() {
    __shared__ float As[GBK][GBM+4];   // row stride 132 floats (528B, 16B aligned)
    __shared__ float Bs[GBK][GBN];
    int tid = threadIdx.x;
    int tx = tid & 15;
    int ty = tid >> 4;
    int row0 = blockIdx.y * GBM;
    int col0 = blockIdx.x * GBN;

    u64t acc[8][4];
    #pragma unroll
    for (int i = 0; i < 8; i++)
        #pragma unroll
        for (int j = 0; j < 4; j++) acc[i][j] = 0ull;

    int am = tid >> 1;              // row within tile for A load
    int akq = (tid & 1) * 4;        // k offset (0 or 4)
    int bk = tid >> 5;              // k row for B load
    int bc = (tid & 31) * 4;        // col for B load

    for (int k0 = 0; k0 < LINn; k0 += GBK) {
        float4 av4 = *(const float4*)&g_feat[(size_t)(row0 + am)*LINn + k0 + akq];
        float4 bv4 = *(const float4*)&g_Bmat[(size_t)(k0 + bk)*GALLn + col0 + bc];
        __syncthreads();
        As[akq+0][am] = av4.x;
        As[akq+1][am] = av4.y;
        As[akq+2][am] = av4.z;
        As[akq+3][am] = av4.w;
        *(float4*)&Bs[bk][bc] = bv4;
        __syncthreads();
        #pragma unroll
        for (int kk = 0; kk < GBK; kk++) {
            float4 a0 = *(const float4*)&As[kk][ty*8];
            float4 a1 = *(const float4*)&As[kk][ty*8 + 4];
            float4 b0 = *(const float4*)&Bs[kk][tx*8];
            float4 b1 = *(const float4*)&Bs[kk][tx*8 + 4];
            u64t bp[4] = { pk2(b0.x,b0.y), pk2(b0.z,b0.w),
                           pk2(b1.x,b1.y), pk2(b1.z,b1.w) };
            float av[8] = {a0.x,a0.y,a0.z,a0.w,a1.x,a1.y,a1.z,a1.w};
            #pragma unroll
            for (int i = 0; i < 8; i++) {
                u64t ad = pk2(av[i], av[i]);
                fma2(acc[i][0], ad, bp[0]);
                fma2(acc[i][1], ad, bp[1]);
                fma2(acc[i][2], ad, bp[2]);
                fma2(acc[i][3], ad, bp[3]);
            }
        }
    }
    float bs[8];
    #pragma unroll
    for (int j = 0; j < 8; j++) bs[j] = g_biascat[col0 + tx*8 + j];
    #pragma unroll
    for (int i = 0; i < 8; i++) {
        float* op = &g_xproj[(size_t)(row0 + ty*8 + i)*GALLn + col0 + tx*8];
        float2 r0 = upk(acc[i][0]);
        float2 r1 = upk(acc[i][1]);
        float2 r2 = upk(acc[i][2]);
        float2 r3 = upk(acc[i][3]);
        float4 o0 = make_float4(r0.x + bs[0], r0.y + bs[1], r1.x + bs[2], r1.y + bs[3]);
        float4 o1 = make_float4(r2.x + bs[4], r2.y + bs[5], r3.x + bs[6], r3.y + bs[7]);
        *(float4*)&op[0] = o0;
        *(float4*)&op[4] = o1;
    }
}

// ---------------- LSTM recurrence, f32x2 gate-pair packed ----------------
// block = 256 thr, 32 samples; thread: 4 samples x 4 units x 4 gates.
// wt layout: [kl][pair*256 + u*2 + sub], row stride 514 (LDS.64 aligned, 2-way STS)
#define RSW 514
#define LSTM_SMEM ((32*129 + 32*RSW)*4)
__device__ __forceinline__ float sigf(float v) { return 1.f / (1.f + __expf(-v)); }
__device__ __forceinline__ float tanhfast(float v) { return 2.f / (1.f + __expf(-2.f*v)) - 1.f; }

__global__ void __launch_bounds__(256, 2) lstm_kernel(const float* __restrict__ w_hh_f,
                                                      const float* __restrict__ w_hh_b) {
    extern __shared__ float sm[];
    float* hs = sm;                 // [32][129]
    float* wt = sm + 32*129;        // [32][RSW]
    int dir = blockIdx.y;
    const float* Whh = dir ? w_hh_b : w_hh_f;
    float* hout = dir ? g_hb : g_hf;
    int b0 = blockIdx.x * 32;
    int tid = threadIdx.x;
    int sg = tid & 7;               // sample group (4 samples each)
    int ug = tid >> 3;              // unit group (4 units each)

    for (int i = tid; i < 32*129; i += 256) hs[i] = 0.f;
    float cReg[4][4];
    #pragma unroll
    for (int si = 0; si < 4; si++)
        #pragma unroll
        for (int q = 0; q < 4; q++) cReg[si][q] = 0.f;
    __syncthreads();

    for (int t = 0; t < Ln; t++) {
        int tt = dir ? (Ln - 1 - t) : t;
        u64t accIF[4][4], accGO[4][4];
        #pragma unroll
        for (int si = 0; si < 4; si++)
            #pragma unroll
            for (int q = 0; q < 4; q++) { accIF[si][q] = 0ull; accGO[si][q] = 0ull; }

        for (int k0 = 0; k0 < Hn; k0 += 32) {
            __syncthreads();
            // stage Whh chunk, pair-interleaved: pair=(gate>>1), sub=(gate&1)
            for (int idx = tid; idx < G4n*32; idx += 256) {
                int g  = idx >> 5, kl = idx & 31;
                int u  = g & 127;
                int gate = g >> 7;
                int pos = ((gate >> 1) << 8) + u*2 + (gate & 1);
                wt[kl*RSW + pos] = Whh[g*Hn + k0 + kl];   // coalesced gmem read
            }
            __syncthreads();
            #pragma unroll 4
            for (int kl = 0; kl < 32; kl++) {
                u64t hd[4];
                #pragma unroll
                for (int si = 0; si < 4; si++) {
                    float hv = hs[(sg*4 + si)*129 + k0 + kl];
                    hd[si] = pk2(hv, hv);
                }
                const float* wrow = &wt[kl*RSW];
                #pragma unroll
                for (int q = 0; q < 4; q++) {
                    int u2 = (ug*4 + q)*2;
                    float2 wIFf = *(const float2*)&wrow[u2];
                    float2 wGOf = *(const float2*)&wrow[256 + u2];
                    u64t wIF = pk2(wIFf.x, wIFf.y);
                    u64t wGO = pk2(wGOf.x, wGOf.y);
                    #pragma unroll
                    for (int si = 0; si < 4; si++) {
                        fma2(accIF[si][q], hd[si], wIF);
                        fma2(accGO[si][q], hd[si], wGO);
                    }
                }
            }
        }
        __syncthreads();   // all hs reads done before updating hs

        #pragma unroll
        for (int si = 0; si < 4; si++) {
            int s = sg*4 + si;
            int n = (b0 + s)*Ln + tt;
            const float* xp = &g_xproj[(size_t)n*GALLn + dir*G4n];
            float4 xi4 = *(const float4*)&xp[ug*4];
            float4 xf4 = *(const float4*)&xp[128 + ug*4];
            float4 xg4 = *(const float4*)&xp[256 + ug*4];
            float4 xo4 = *(const float4*)&xp[384 + ug*4];
            float xi_[4] = {xi4.x, xi4.y, xi4.z, xi4.w};
            float xf_[4] = {xf4.x, xf4.y, xf4.z, xf4.w};
            float xg_[4] = {xg4.x, xg4.y, xg4.z, xg4.w};
            float xo_[4] = {xo4.x, xo4.y, xo4.z, xo4.w};
            float hv4[4];
            #pragma unroll
            for (int q = 0; q < 4; q++) {
                float2 vIF = upk(accIF[si][q]);
                float2 vGO = upk(accGO[si][q]);
                float zi = vIF.x + xi_[q];
                float zf = vIF.y + xf_[q];
                float zg = vGO.x + xg_[q];
                float zo = vGO.y + xo_[q];
                float cn = sigf(zf)*cReg[si][q] + sigf(zi)*tanhfast(zg);
                float hn = sigf(zo)*tanhfast(cn);
                cReg[si][q] = cn;
                hs[s*129 + ug*4 + q] = hn;
                hv4[q] = hn;
            }
            *(float4*)&hout[(size_t)n*Hn + ug*4] =
                make_float4(hv4[0], hv4[1], hv4[2], hv4[3]);
        }
        __syncthreads();
    }
}

// ---------------- emissions: bn2+fc folded, warp per token ----------------
__global__ void emis_kernel() {
    int gtid = blockIdx.x*blockDim.x + threadIdx.x;
    int w = gtid >> 5;
    int lane = gtid & 31;
    if (w >= Nn) return;
    float a0 = 0.f, a1 = 0.f, a2 = 0.f;
    for (int j = lane; j < 2*Hn; j += 32) {
        float hv = (j < Hn) ? g_hf[(size_t)w*Hn + j] : g_hb[(size_t)w*Hn + j - Hn];
        a0 += hv * g_fcw2[0*2*Hn + j];
        a1 += hv * g_fcw2[1*2*Hn + j];
        a2 += hv * g_fcw2[2*2*Hn + j];
    }
    #pragma unroll
    for (int off = 16; off; off >>= 1) {
        a0 += __shfl_xor_sync(0xffffffffu, a0, off);
        a1 += __shfl_xor_sync(0xffffffffu, a1, off);
        a2 += __shfl_xor_sync(0xffffffffu, a2, off);
    }
    if (lane == 0) {
        g_emis[w*Tn + 0] = a0 + g_fcb2[0];
        g_emis[w*Tn + 1] = a1 + g_fcb2[1];
        g_emis[w*Tn + 2] = a2 + g_fcb2[2];
    }
}

// ---------------- viterbi: one thread per sample ----------------
__global__ void viterbi_kernel(const int* __restrict__ x,
                               const float* __restrict__ trans,
                               const float* __restrict__ start_t,
                               const float* __restrict__ end_t,
                               float* __restrict__ out) {
    int b = blockIdx.x*blockDim.x + threadIdx.x;
    if (b >= Bn) return;
    float tr[Tn][Tn];
    #pragma unroll
    for (int i = 0; i < Tn; i++)
        #pragma unroll
        for (int j = 0; j < Tn; j++) tr[i][j] = trans[i*Tn + j];

    float sc[Tn];
    #pragma unroll
    for (int j = 0; j < Tn; j++) sc[j] = start_t[j] + g_emis[(b*Ln)*Tn + j];

    unsigned char hist[Ln-1][Tn];
    for (int t = 1; t < Ln; t++) {
        bool m = x[(b*Ln + t)*Wn + 2] > 0;
        float ns[Tn];
        #pragma unroll
        for (int j = 0; j < Tn; j++) {
            float best = sc[0] + tr[0][j];
            int bi = 0;
            #pragma unroll
            for (int i = 1; i < Tn; i++) {
                float v = sc[i] + tr[i][j];
                if (v > best) { best = v; bi = i; }
            }
            hist[t-1][j] = (unsigned char)bi;
            ns[j] = best + g_emis[(b*Ln + t)*Tn + j];
        }
        if (m) {
            #pragma unroll
            for (int j = 0; j < Tn; j++) sc[j] = ns[j];
        }
    }
    #pragma unroll
    for (int j = 0; j < Tn; j++) sc[j] += end_t[j];
    float best = sc[0];
    int last = 0;
    #pragma unroll
    for (int j = 1; j < Tn; j++) if (sc[j] > best) { best = sc[j]; last = j; }

    int tags[Ln];
    tags[Ln-1] = last;
    int tag = last;
    for (int t = Ln-1; t >= 1; t--) {
        bool m = x[(b*Ln + t)*Wn + 2] > 0;
        int prev = hist[t-1][tag];
        if (m) tag = prev;
        tags[t-1] = tag;
    }
    out[b] = best;
    float* to = out + Bn + (size_t)b*Ln;
    for (int l = 0; l < Ln; l++) to[l] = (float)tags[l];
}

// ---------------- launch ----------------
extern "C" void kernel_launch(void* const* d_in, const int* in_sizes, int n_in,
                              void* d_out, int out_size) {
    const int*   x      = (const int*)  d_in[0];
    const float* emb    = (const float*)d_in[1];
    const float* conv_w = (const float*)d_in[2];
    const float* conv_b = (const float*)d_in[3];
    const float* bn1_g  = (const float*)d_in[4];
    const float* bn1_b  = (const float*)d_in[5];
    const float* bn1_m  = (const float*)d_in[6];
    const float* bn1_v  = (const float*)d_in[7];
    const float* w_ih_f = (const float*)d_in[8];
    const float* w_hh_f = (const float*)d_in[9];
    const float* b_f    = (const float*)d_in[10];
    const float* w_ih_b = (const float*)d_in[11];
    const float* w_hh_b = (const float*)d_in[12];
    const float* b_b    = (const float*)d_in[13];
    const float* bn2_g  = (const float*)d_in[14];
    const float* bn2_b  = (const float*)d_in[15];
    const float* bn2_m  = (const float*)d_in[16];
    const float* bn2_v  = (const float*)d_in[17];
    const float* fc_w   = (const float*)d_in[18];
    const float* fc_b   = (const float*)d_in[19];
    const float* trans  = (const float*)d_in[20];
    const float* startt = (const float*)d_in[21];
    const float* endt   = (const float*)d_in[22];
    float* out = (float*)d_out;

    prep_small<<<1, 256>>>(conv_b, bn1_g, bn1_b, bn1_m, bn1_v,
                           bn2_g, bn2_b, bn2_m, bn2_v, fc_w, fc_b, b_f, b_b);
    prep_P<<<(An*Cn*3 + 255)/256, 256>>>(emb, conv_w);
    prep_Bmat<<<(LINn*GALLn + 255)/256, 256>>>(w_ih_f, w_ih_b);
    feat_kernel<<<(Nn*Cn + 255)/256, 256>>>(x);
    gemm_kernel<<<dim3(GALLn/GBN, Nn/GBM), 256>>>();
    cudaFuncSetAttribute(lstm_kernel, cudaFuncAttributeMaxDynamicSharedMemorySize, LSTM_SMEM);
    lstm_kernel<<<dim3(Bn/32, 2), 256, LSTM_SMEM>>>(w_hh_f, w_hh_b);
    emis_kernel<<<(Nn*32 + 255)/256, 256>>>();
    viterbi_kernel<<<(Bn + 255)/256, 256>>>(x, trans, startt, endt, out);
}